// round 1
// baseline (speedup 1.0000x reference)
#include <cuda_runtime.h>
#include <math.h>

#define NPIX 16384   // H*W
#define TOK  128     // tokens per chunk (= W)

__device__ float g_te[8 * 1024];   // pooled text_embed [B, 1024]
__device__ float g_film[8 * 128];  // gamma|beta per batch

// ---------------------------------------------------------------------------
// Kernel 0a: adaptive_avg_pool2d(text_embed, (4,4)) -> g_te  (deterministic)
// one block per (b, c): 512 blocks
// ---------------------------------------------------------------------------
__global__ void __launch_bounds__(256) pool_kernel(const float* __restrict__ te) {
    __shared__ float sbw[8 * 4];  // per-warp partials: warp w owns j = w&3, 4 i-buckets
    const int tid = threadIdx.x;
    const int warp = tid >> 5;
    const int lane = tid & 31;
    const float* src = te + (size_t)blockIdx.x * NPIX;

    float lacc[4] = {0.f, 0.f, 0.f, 0.f};
    for (int i = tid; i < NPIX; i += 256) {
        float v = src[i];
        int hh = i >> 7;
        lacc[hh >> 5] += v;
    }
    // warp reduce each of the 4 partials (all lanes in a warp share the same j)
    #pragma unroll
    for (int ii = 0; ii < 4; ii++) {
        float v = lacc[ii];
        for (int off = 16; off; off >>= 1) v += __shfl_down_sync(0xffffffffu, v, off);
        lacc[ii] = v;
    }
    if (lane == 0) {
        #pragma unroll
        for (int ii = 0; ii < 4; ii++) sbw[warp * 4 + ii] = lacc[ii];
    }
    __syncthreads();
    if (tid < 16) {
        int i_ = tid >> 2, j_ = tid & 3;
        // warps with (w & 3) == j_ are w = j_ and j_+4
        float val = sbw[j_ * 4 + i_] + sbw[(j_ + 4) * 4 + i_];
        int b = blockIdx.x >> 6, c = blockIdx.x & 63;
        g_te[b * 1024 + c * 16 + i_ * 4 + j_] = val * (1.0f / 1024.0f);
    }
}

// ---------------------------------------------------------------------------
// Kernel 0b: FiLM MLP  te[1024] -> leaky_relu -> [128] -> g_film
// one block per batch, 128 threads
// ---------------------------------------------------------------------------
__global__ void __launch_bounds__(128) film_kernel(
    const float* __restrict__ m1w, const float* __restrict__ m1b,
    const float* __restrict__ m2w, const float* __restrict__ m2b) {
    __shared__ float ste[1024];
    __shared__ float shm[128];
    const int b = blockIdx.x, tid = threadIdx.x;
    for (int i = tid; i < 1024; i += 128) ste[i] = g_te[b * 1024 + i];
    __syncthreads();
    float acc = m1b[tid];
    for (int k = 0; k < 1024; k++) acc = fmaf(ste[k], m1w[k * 128 + tid], acc);
    shm[tid] = acc > 0.f ? acc : 0.01f * acc;
    __syncthreads();
    float acc2 = m2b[tid];
    #pragma unroll 4
    for (int k = 0; k < 128; k++) acc2 = fmaf(shm[k], m2w[k * 128 + tid], acc2);
    g_film[b * 128 + tid] = acc2;
}

// ---------------------------------------------------------------------------
// Fused per-(batch,row) megakernel
// ---------------------------------------------------------------------------
constexpr int SZ = 8704;                         // floats per tile region (128*68)
constexpr int SMEM_FLOATS = 5 * SZ + 12288 + 384;
constexpr int SMEM_BYTES = SMEM_FLOATS * 4;      // 224768 B

// out[t][o] = sum_c in[t*INS + c] * w[c*WS + o]; epi consumes acc
template <int INS, int WS, typename Epi>
__device__ __forceinline__ void gemm64(const float* __restrict__ in,
                                       const float* __restrict__ w, Epi epi) {
    const int to = 4 * (threadIdx.x & 15);
    const int tt = 8 * (threadIdx.x >> 4);
    float acc[8][4];
    #pragma unroll
    for (int i = 0; i < 8; i++)
        #pragma unroll
        for (int j = 0; j < 4; j++) acc[i][j] = 0.f;
    #pragma unroll 2
    for (int c = 0; c < 64; c += 4) {
        float wr[4][4];
        #pragma unroll
        for (int cc = 0; cc < 4; cc++) {
            float4 wv = *reinterpret_cast<const float4*>(&w[(c + cc) * WS + to]);
            wr[cc][0] = wv.x; wr[cc][1] = wv.y; wr[cc][2] = wv.z; wr[cc][3] = wv.w;
        }
        #pragma unroll
        for (int i = 0; i < 8; i++) {
            float4 av = *reinterpret_cast<const float4*>(&in[(tt + i) * INS + c]);
            float ar[4] = {av.x, av.y, av.z, av.w};
            #pragma unroll
            for (int cc = 0; cc < 4; cc++)
                #pragma unroll
                for (int j = 0; j < 4; j++)
                    acc[i][j] = fmaf(ar[cc], wr[cc][j], acc[i][j]);
        }
    }
    epi(tt, to, acc);
}

__global__ void __launch_bounds__(256) fused_kernel(
    const float* __restrict__ x, const float* __restrict__ te,
    const float* __restrict__ qw, const float* __restrict__ qb,
    const float* __restrict__ kw, const float* __restrict__ kb,
    const float* __restrict__ vw, const float* __restrict__ vb,
    const float* __restrict__ ow, const float* __restrict__ ob,
    const float* __restrict__ ln1w, const float* __restrict__ ln1b,
    const float* __restrict__ ln2w, const float* __restrict__ ln2b,
    const float* __restrict__ fc1w, const float* __restrict__ fc1b,
    const float* __restrict__ fc2w, const float* __restrict__ fc2b,
    const float* __restrict__ cw, const float* __restrict__ cb,
    float* __restrict__ out) {
    extern __shared__ __align__(16) float s[];
    float* sP = s;            // prior -> h           (stride 68)
    float* sX = s + SZ;       // x                    (stride 68)
    float* sA = s + 2 * SZ;   // K / hn (64) -> out (68)
    float* sQ = s + 3 * SZ;   // LNed-Q input? no: Q / attn / t1 (stride 64)
    float* sV = s + 4 * SZ;   // LN1(prior) / V / ffn_acc (stride 64)
    float* sW = s + 5 * SZ;   // weight stage (<=12288 floats)
    float* sMu = sW + 12288;  // [128]
    float* sRs = sMu + 128;   // [128]
    float* sGm = sRs + 128;   // [64]
    float* sBt = sGm + 64;    // [64]

    const int tid = threadIdx.x;
    const int b = blockIdx.x >> 7;
    const int row = blockIdx.x & 127;
    const size_t base = (size_t)b * 64 * NPIX + (size_t)row * 128;  // + c*NPIX + w

    // ---- Phase A: load x / prior tiles (token-major, stride 68) + QKV weights
    for (int i = tid; i < 8192; i += 256) {
        int c = i >> 7, w_ = i & 127;
        sX[w_ * 68 + c] = x[base + (size_t)c * NPIX + w_];
        sP[w_ * 68 + c] = te[base + (size_t)c * NPIX + w_];
    }
    for (int i = tid; i < 4096; i += 256) {
        sW[i] = qw[i];
        sW[4096 + i] = kw[i];
        sW[8192 + i] = vw[i];
    }
    __syncthreads();

    // ---- LN1 stats over channels per token
    if (tid < 128) {
        float sum = 0.f, sq = 0.f;
        const float* rowp = sP + tid * 68;
        #pragma unroll
        for (int c = 0; c < 64; c += 4) {
            float4 v = *reinterpret_cast<const float4*>(rowp + c);
            sum += v.x + v.y + v.z + v.w;
            sq += v.x * v.x + v.y * v.y + v.z * v.z + v.w * v.w;
        }
        float mu = sum * (1.f / 64.f);
        float var = fmaxf(sq * (1.f / 64.f) - mu * mu, 0.f);
        sMu[tid] = mu;
        sRs[tid] = rsqrtf(var + 1e-5f);
    }
    __syncthreads();
    // LN1(prior) -> sV (stride 64)
    for (int i = tid; i < 8192; i += 256) {
        int t = i >> 6, c = i & 63;
        sV[t * 64 + c] = (sP[t * 68 + c] - sMu[t]) * sRs[t] * ln1w[c] + ln1b[c];
    }
    __syncthreads();

    // ---- Q = LN1 @ qw + qb -> sQ
    gemm64<64, 64>(sV, sW, [&](int tt, int to, float (&acc)[8][4]) {
        #pragma unroll
        for (int i = 0; i < 8; i++)
            #pragma unroll
            for (int j = 0; j < 4; j++)
                sQ[(tt + i) * 64 + to + j] = acc[i][j] + qb[to + j];
    });
    __syncthreads();

    // ---- K -> sA, V -> sV (overwrites LN1, dead now)
    gemm64<68, 64>(sX, sW + 4096, [&](int tt, int to, float (&acc)[8][4]) {
        #pragma unroll
        for (int i = 0; i < 8; i++)
            #pragma unroll
            for (int j = 0; j < 4; j++)
                sA[(tt + i) * 64 + to + j] = acc[i][j] + kb[to + j];
    });
    gemm64<68, 64>(sX, sW + 8192, [&](int tt, int to, float (&acc)[8][4]) {
        #pragma unroll
        for (int i = 0; i < 8; i++)
            #pragma unroll
            for (int j = 0; j < 4; j++)
                sV[(tt + i) * 64 + to + j] = acc[i][j] + vb[to + j];
    });
    __syncthreads();

    // ---- load o_w (sW free), then attention. 2048 rows of (head, q); 8/thread
    for (int i = tid; i < 4096; i += 256) sW[i] = ow[i];
    #pragma unroll 1
    for (int it = 0; it < 8; it++) {
        int r = it * 256 + tid;
        int hh = r >> 7, q = r & 127;
        float4 qv = *reinterpret_cast<const float4*>(sQ + q * 64 + hh * 4);
        qv.x *= 0.5f; qv.y *= 0.5f; qv.z *= 0.5f; qv.w *= 0.5f;  // 1/sqrt(head_dim)
        float l = 0.f, a0 = 0.f, a1 = 0.f, a2 = 0.f, a3 = 0.f;
        #pragma unroll 4
        for (int k = 0; k < 128; k++) {
            float4 kv = *reinterpret_cast<const float4*>(sA + k * 64 + hh * 4);
            float sc = qv.x * kv.x + qv.y * kv.y + qv.z * kv.z + qv.w * kv.w;
            float p = __expf(fminf(sc, 30.f));  // scores ~N(0,0.05): no max needed
            float4 vv = *reinterpret_cast<const float4*>(sV + k * 64 + hh * 4);
            l += p;
            a0 = fmaf(p, vv.x, a0); a1 = fmaf(p, vv.y, a1);
            a2 = fmaf(p, vv.z, a2); a3 = fmaf(p, vv.w, a3);
        }
        float inv = __fdividef(1.f, l);
        *reinterpret_cast<float4*>(sQ + q * 64 + hh * 4) =
            make_float4(a0 * inv, a1 * inv, a2 * inv, a3 * inv);
    }
    __syncthreads();

    // ---- h = attn @ ow + ob + prior   (in-place into sP)
    gemm64<64, 64>(sQ, sW, [&](int tt, int to, float (&acc)[8][4]) {
        #pragma unroll
        for (int i = 0; i < 8; i++)
            #pragma unroll
            for (int j = 0; j < 4; j++) {
                float v = acc[i][j] + ob[to + j] + sP[(tt + i) * 68 + to + j];
                sP[(tt + i) * 68 + to + j] = v;
            }
    });
    __syncthreads();

    // ---- LN2 stats on h
    if (tid < 128) {
        float sum = 0.f, sq = 0.f;
        const float* rowp = sP + tid * 68;
        #pragma unroll
        for (int c = 0; c < 64; c += 4) {
            float4 v = *reinterpret_cast<const float4*>(rowp + c);
            sum += v.x + v.y + v.z + v.w;
            sq += v.x * v.x + v.y * v.y + v.z * v.z + v.w * v.w;
        }
        float mu = sum * (1.f / 64.f);
        float var = fmaxf(sq * (1.f / 64.f) - mu * mu, 0.f);
        sMu[tid] = mu;
        sRs[tid] = rsqrtf(var + 1e-5f);
    }
    __syncthreads();
    // hn -> sA (stride 64); ffn accumulator init with fc2 bias -> sV
    for (int i = tid; i < 8192; i += 256) {
        int t = i >> 6, c = i & 63;
        sA[t * 64 + c] = (sP[t * 68 + c] - sMu[t]) * sRs[t] * ln2w[c] + ln2b[c];
        sV[t * 64 + c] = fc2b[c];
    }
    __syncthreads();

    // ---- FFN in 4 j-blocks of 64: t1 = gelu(hn@fc1_blk+b); acc += t1@fc2_blk
    for (int jb = 0; jb < 4; jb++) {
        for (int i = tid; i < 4096; i += 256) {
            int c = i >> 6, j = i & 63;
            sW[i] = fc1w[c * 256 + jb * 64 + j];   // fc1 block [64c][64j]
            sW[4096 + i] = fc2w[jb * 4096 + i];    // fc2 block [64j][64o]
        }
        __syncthreads();
        const float* f1b = fc1b + jb * 64;
        gemm64<64, 64>(sA, sW, [&](int tt, int to, float (&acc)[8][4]) {
            #pragma unroll
            for (int i = 0; i < 8; i++)
                #pragma unroll
                for (int j = 0; j < 4; j++) {
                    float v = acc[i][j] + f1b[to + j];
                    sQ[(tt + i) * 64 + to + j] =
                        0.5f * v * (1.f + erff(v * 0.70710678118654752f));
                }
        });
        __syncthreads();
        gemm64<64, 64>(sQ, sW + 4096, [&](int tt, int to, float (&acc)[8][4]) {
            #pragma unroll
            for (int i = 0; i < 8; i++)
                #pragma unroll
                for (int j = 0; j < 4; j++)
                    sV[(tt + i) * 64 + to + j] += acc[i][j];
        });
        __syncthreads();
    }

    // ---- h += ffn; stage conv_w transposed (stride 68); load gamma/beta
    for (int i = tid; i < 8192; i += 256) {
        int t = i >> 6, c = i & 63;
        sP[t * 68 + c] += sV[t * 64 + c];
    }
    for (int i = tid; i < 4096; i += 256) {
        int o = i >> 6, ii = i & 63;
        sW[ii * 68 + o] = cw[i];  // conv_w is [out,in] -> transpose to [in][out]
    }
    if (tid < 64) {
        sGm[tid] = g_film[b * 128 + tid];
        sBt[tid] = g_film[b * 128 + 64 + tid];
    }
    __syncthreads();

    // ---- conv(1x1) + conv_b + x, then FiLM: (1+g)*v + beta  -> sA (stride 68)
    gemm64<68, 68>(sP, sW, [&](int tt, int to, float (&acc)[8][4]) {
        #pragma unroll
        for (int i = 0; i < 8; i++)
            #pragma unroll
            for (int j = 0; j < 4; j++) {
                float v = acc[i][j] + cb[to + j] + sX[(tt + i) * 68 + to + j];
                sA[(tt + i) * 68 + to + j] = v + sGm[to + j] * v + sBt[to + j];
            }
    });
    __syncthreads();

    // ---- write out coalesced channel-major
    for (int i = tid; i < 8192; i += 256) {
        int c = i >> 7, w_ = i & 127;
        out[base + (size_t)c * NPIX + w_] = sA[w_ * 68 + c];
    }
}

// ---------------------------------------------------------------------------
extern "C" void kernel_launch(void* const* d_in, const int* in_sizes, int n_in,
                              void* d_out, int out_size) {
    const float* x    = (const float*)d_in[0];
    const float* te   = (const float*)d_in[1];
    const float* qw   = (const float*)d_in[2];
    const float* qb   = (const float*)d_in[3];
    const float* kw   = (const float*)d_in[4];
    const float* kb   = (const float*)d_in[5];
    const float* vw   = (const float*)d_in[6];
    const float* vb   = (const float*)d_in[7];
    const float* ow   = (const float*)d_in[8];
    const float* ob   = (const float*)d_in[9];
    const float* ln1w = (const float*)d_in[10];
    const float* ln1b = (const float*)d_in[11];
    const float* ln2w = (const float*)d_in[12];
    const float* ln2b = (const float*)d_in[13];
    const float* fc1w = (const float*)d_in[14];
    const float* fc1b = (const float*)d_in[15];
    const float* fc2w = (const float*)d_in[16];
    const float* fc2b = (const float*)d_in[17];
    const float* cw   = (const float*)d_in[18];
    const float* cb   = (const float*)d_in[19];
    const float* m1w  = (const float*)d_in[20];
    const float* m1b  = (const float*)d_in[21];
    const float* m2w  = (const float*)d_in[22];
    const float* m2b  = (const float*)d_in[23];
    float* out = (float*)d_out;

    cudaFuncSetAttribute(fused_kernel, cudaFuncAttributeMaxDynamicSharedMemorySize,
                         SMEM_BYTES);

    pool_kernel<<<512, 256>>>(te);
    film_kernel<<<8, 128>>>(m1w, m1b, m2w, m2b);
    fused_kernel<<<1024, 256, SMEM_BYTES>>>(x, te, qw, qb, kw, kb, vw, vb, ow, ob,
                                            ln1w, ln1b, ln2w, ln2b, fc1w, fc1b,
                                            fc2w, fc2b, cw, cb, out);
}

// round 2
// speedup vs baseline: 1.0830x; 1.0830x over previous
#include <cuda_runtime.h>
#include <math.h>

#define NPIX 16384   // H*W
#define TOK  128     // tokens per chunk (= W)

__device__ float g_te[8 * 1024];   // pooled text_embed [B, 1024]
__device__ float g_film[8 * 128];  // gamma|beta per batch

// ---------------- packed f32x2 helpers (Blackwell FFMA2) --------------------
__device__ __forceinline__ unsigned long long pk2(float a, float b) {
    unsigned long long r;
    asm("mov.b64 %0, {%1, %2};" : "=l"(r) : "f"(a), "f"(b));
    return r;
}
__device__ __forceinline__ float2 upk(unsigned long long a) {
    float2 f;
    asm("mov.b64 {%0, %1}, %2;" : "=f"(f.x), "=f"(f.y) : "l"(a));
    return f;
}
__device__ __forceinline__ unsigned long long ffma2(unsigned long long a,
                                                    unsigned long long b,
                                                    unsigned long long c) {
    unsigned long long d;
    asm("fma.rn.f32x2 %0, %1, %2, %3;" : "=l"(d) : "l"(a), "l"(b), "l"(c));
    return d;
}
__device__ __forceinline__ unsigned long long fmul2(unsigned long long a,
                                                    unsigned long long b) {
    unsigned long long d;
    asm("mul.rn.f32x2 %0, %1, %2;" : "=l"(d) : "l"(a), "l"(b));
    return d;
}

// ---------------------------------------------------------------------------
// Kernel 0a: adaptive_avg_pool2d(text_embed, (4,4)) -> g_te
// one block per (b, c, i_cell): 2048 blocks x 128 threads.
// thread col = tid (constant), warp w owns j-cell = w.
// ---------------------------------------------------------------------------
__global__ void __launch_bounds__(128) pool_kernel(const float* __restrict__ te) {
    const int tid = threadIdx.x;
    const int lane = tid & 31;
    const int jc = tid >> 5;                 // j cell = warp id
    const int ic = blockIdx.x & 3;           // i cell
    const int c = (blockIdx.x >> 2) & 63;
    const int b = blockIdx.x >> 8;
    const float* src = te + ((size_t)(b * 64 + c)) * NPIX + (size_t)(ic * 32) * 128 + tid;
    float acc = 0.f;
    #pragma unroll 8
    for (int r = 0; r < 32; r++) acc += src[r * 128];
    for (int off = 16; off; off >>= 1) acc += __shfl_down_sync(0xffffffffu, acc, off);
    if (lane == 0)
        g_te[b * 1024 + c * 16 + ic * 4 + jc] = acc * (1.0f / 1024.0f);
}

// ---------------------------------------------------------------------------
// Kernel 0b: FiLM MLP  te[1024] -> leaky_relu -> [128] -> g_film
// ---------------------------------------------------------------------------
__global__ void __launch_bounds__(128) film_kernel(
    const float* __restrict__ m1w, const float* __restrict__ m1b,
    const float* __restrict__ m2w, const float* __restrict__ m2b) {
    __shared__ float ste[1024];
    __shared__ float shm[128];
    const int b = blockIdx.x, tid = threadIdx.x;
    for (int i = tid; i < 1024; i += 128) ste[i] = g_te[b * 1024 + i];
    __syncthreads();
    float acc = m1b[tid];
    for (int k = 0; k < 1024; k++) acc = fmaf(ste[k], m1w[k * 128 + tid], acc);
    shm[tid] = acc > 0.f ? acc : 0.01f * acc;
    __syncthreads();
    float acc2 = m2b[tid];
    #pragma unroll 4
    for (int k = 0; k < 128; k++) acc2 = fmaf(shm[k], m2w[k * 128 + tid], acc2);
    g_film[b * 128 + tid] = acc2;
}

// ---------------------------------------------------------------------------
// Fused per-(batch,row) megakernel
// ---------------------------------------------------------------------------
constexpr int SZ = 8704;                         // floats per tile region (128*68)
constexpr int SMEM_FLOATS = 5 * SZ + 12288 + 384;
constexpr int SMEM_BYTES = SMEM_FLOATS * 4;      // 224768 B

// out[t][o] = sum_c in[t*INS + c] * w[c*WS + o]; packed FFMA2 inner loop.
// epi receives acc as float4 per row.
template <int INS, int WS, typename Epi>
__device__ __forceinline__ void gemm64(const float* __restrict__ in,
                                       const float* __restrict__ w, Epi epi) {
    const int to = 4 * (threadIdx.x & 15);
    const int tt = 8 * (threadIdx.x >> 4);
    unsigned long long acc0[8], acc1[8];
    #pragma unroll
    for (int i = 0; i < 8; i++) { acc0[i] = 0ULL; acc1[i] = 0ULL; }
    #pragma unroll 2
    for (int c = 0; c < 64; c += 4) {
        unsigned long long wp0[4], wp1[4];
        #pragma unroll
        for (int cc = 0; cc < 4; cc++) {
            ulonglong2 wv = *reinterpret_cast<const ulonglong2*>(&w[(c + cc) * WS + to]);
            wp0[cc] = wv.x; wp1[cc] = wv.y;
        }
        #pragma unroll
        for (int i = 0; i < 8; i++) {
            float4 av = *reinterpret_cast<const float4*>(&in[(tt + i) * INS + c]);
            unsigned long long a;
            a = pk2(av.x, av.x);
            acc0[i] = ffma2(a, wp0[0], acc0[i]); acc1[i] = ffma2(a, wp1[0], acc1[i]);
            a = pk2(av.y, av.y);
            acc0[i] = ffma2(a, wp0[1], acc0[i]); acc1[i] = ffma2(a, wp1[1], acc1[i]);
            a = pk2(av.z, av.z);
            acc0[i] = ffma2(a, wp0[2], acc0[i]); acc1[i] = ffma2(a, wp1[2], acc1[i]);
            a = pk2(av.w, av.w);
            acc0[i] = ffma2(a, wp0[3], acc0[i]); acc1[i] = ffma2(a, wp1[3], acc1[i]);
        }
    }
    float4 a4[8];
    #pragma unroll
    for (int i = 0; i < 8; i++) {
        float2 lo = upk(acc0[i]), hi = upk(acc1[i]);
        a4[i] = make_float4(lo.x, lo.y, hi.x, hi.y);
    }
    epi(tt, to, a4);
}

__global__ void __launch_bounds__(256) fused_kernel(
    const float* __restrict__ x, const float* __restrict__ te,
    const float* __restrict__ qw, const float* __restrict__ qb,
    const float* __restrict__ kw, const float* __restrict__ kb,
    const float* __restrict__ vw, const float* __restrict__ vb,
    const float* __restrict__ ow, const float* __restrict__ ob,
    const float* __restrict__ ln1w, const float* __restrict__ ln1b,
    const float* __restrict__ ln2w, const float* __restrict__ ln2b,
    const float* __restrict__ fc1w, const float* __restrict__ fc1b,
    const float* __restrict__ fc2w, const float* __restrict__ fc2b,
    const float* __restrict__ cw, const float* __restrict__ cb,
    float* __restrict__ out) {
    extern __shared__ __align__(16) float s[];
    float* sP = s;            // prior -> h           (stride 68)
    float* sX = s + SZ;       // x                    (stride 68)
    float* sA = s + 2 * SZ;   // K / hn (64) -> out (68)
    float* sQ = s + 3 * SZ;   // Q / attn / t1        (stride 64)
    float* sV = s + 4 * SZ;   // LN1(prior) / V / ffn_acc (stride 64)
    float* sW = s + 5 * SZ;   // weight stage (<=12288 floats)
    float* sMu = sW + 12288;  // [128]
    float* sRs = sMu + 128;   // [128]
    float* sGm = sRs + 128;   // [64]
    float* sBt = sGm + 64;    // [64]

    const int tid = threadIdx.x;
    const int b = blockIdx.x >> 7;
    const int row = blockIdx.x & 127;
    const size_t base = (size_t)b * 64 * NPIX + (size_t)row * 128;  // + c*NPIX + w

    // ---- Phase A: load x / prior tiles (token-major, stride 68) + QKV weights
    for (int i = tid; i < 8192; i += 256) {
        int c = i >> 7, w_ = i & 127;
        sX[w_ * 68 + c] = x[base + (size_t)c * NPIX + w_];
        sP[w_ * 68 + c] = te[base + (size_t)c * NPIX + w_];
    }
    for (int i = tid; i < 1024; i += 256) {
        reinterpret_cast<float4*>(sW)[i] = reinterpret_cast<const float4*>(qw)[i];
        reinterpret_cast<float4*>(sW + 4096)[i] = reinterpret_cast<const float4*>(kw)[i];
        reinterpret_cast<float4*>(sW + 8192)[i] = reinterpret_cast<const float4*>(vw)[i];
    }
    __syncthreads();

    // ---- LN1 stats over channels per token
    if (tid < 128) {
        float sum = 0.f, sq = 0.f;
        const float* rowp = sP + tid * 68;
        #pragma unroll
        for (int c = 0; c < 64; c += 4) {
            float4 v = *reinterpret_cast<const float4*>(rowp + c);
            sum += v.x + v.y + v.z + v.w;
            sq += v.x * v.x + v.y * v.y + v.z * v.z + v.w * v.w;
        }
        float mu = sum * (1.f / 64.f);
        float var = fmaxf(sq * (1.f / 64.f) - mu * mu, 0.f);
        sMu[tid] = mu;
        sRs[tid] = rsqrtf(var + 1e-5f);
    }
    __syncthreads();
    // LN1(prior) -> sV (stride 64)
    for (int i = tid; i < 2048; i += 256) {
        int t = i >> 4, c4 = (i & 15) * 4;
        float4 p = *reinterpret_cast<const float4*>(&sP[t * 68 + c4]);
        float4 w1 = *reinterpret_cast<const float4*>(&ln1w[c4]);
        float4 b1 = *reinterpret_cast<const float4*>(&ln1b[c4]);
        float mu = sMu[t], rs = sRs[t];
        float4 o;
        o.x = (p.x - mu) * rs * w1.x + b1.x;
        o.y = (p.y - mu) * rs * w1.y + b1.y;
        o.z = (p.z - mu) * rs * w1.z + b1.z;
        o.w = (p.w - mu) * rs * w1.w + b1.w;
        *reinterpret_cast<float4*>(&sV[t * 64 + c4]) = o;
    }
    __syncthreads();

    // ---- Q = LN1 @ qw + qb -> sQ
    gemm64<64, 64>(sV, sW, [&](int tt, int to, float4 (&a4)[8]) {
        float4 bq = *reinterpret_cast<const float4*>(&qb[to]);
        #pragma unroll
        for (int i = 0; i < 8; i++) {
            float4 r = a4[i];
            r.x += bq.x; r.y += bq.y; r.z += bq.z; r.w += bq.w;
            *reinterpret_cast<float4*>(&sQ[(tt + i) * 64 + to]) = r;
        }
    });
    __syncthreads();

    // ---- K -> sA, V -> sV (overwrites LN1, dead now)
    gemm64<68, 64>(sX, sW + 4096, [&](int tt, int to, float4 (&a4)[8]) {
        float4 bk = *reinterpret_cast<const float4*>(&kb[to]);
        #pragma unroll
        for (int i = 0; i < 8; i++) {
            float4 r = a4[i];
            r.x += bk.x; r.y += bk.y; r.z += bk.z; r.w += bk.w;
            *reinterpret_cast<float4*>(&sA[(tt + i) * 64 + to]) = r;
        }
    });
    gemm64<68, 64>(sX, sW + 8192, [&](int tt, int to, float4 (&a4)[8]) {
        float4 bv = *reinterpret_cast<const float4*>(&vb[to]);
        #pragma unroll
        for (int i = 0; i < 8; i++) {
            float4 r = a4[i];
            r.x += bv.x; r.y += bv.y; r.z += bv.z; r.w += bv.w;
            *reinterpret_cast<float4*>(&sV[(tt + i) * 64 + to]) = r;
        }
    });
    __syncthreads();

    // ---- load o_w (sW free), then attention. 2048 rows of (head, q); 8/thread
    for (int i = tid; i < 1024; i += 256)
        reinterpret_cast<float4*>(sW)[i] = reinterpret_cast<const float4*>(ow)[i];
    #pragma unroll 1
    for (int it = 0; it < 8; it++) {
        int r = it * 256 + tid;
        int hh = r >> 7, q = r & 127;
        float4 qv = *reinterpret_cast<const float4*>(sQ + q * 64 + hh * 4);
        unsigned long long q01 = pk2(qv.x * 0.5f, qv.y * 0.5f);   // 1/sqrt(hd)=0.5
        unsigned long long q23 = pk2(qv.z * 0.5f, qv.w * 0.5f);
        float l = 0.f;
        unsigned long long a01 = 0ULL, a23 = 0ULL;
        #pragma unroll 4
        for (int k = 0; k < 128; k++) {
            ulonglong2 kv = *reinterpret_cast<const ulonglong2*>(sA + k * 64 + hh * 4);
            unsigned long long pp = ffma2(q23, kv.y, fmul2(q01, kv.x));
            float2 pf = upk(pp);
            float sc = pf.x + pf.y;
            float e = __expf(fminf(sc, 30.f));   // scores ~N(0,0.05): no max pass
            ulonglong2 vv = *reinterpret_cast<const ulonglong2*>(sV + k * 64 + hh * 4);
            unsigned long long ed = pk2(e, e);
            l += e;
            a01 = ffma2(ed, vv.x, a01);
            a23 = ffma2(ed, vv.y, a23);
        }
        float inv = __fdividef(1.f, l);
        float2 f01 = upk(a01), f23 = upk(a23);
        *reinterpret_cast<float4*>(sQ + q * 64 + hh * 4) =
            make_float4(f01.x * inv, f01.y * inv, f23.x * inv, f23.y * inv);
    }
    __syncthreads();

    // ---- h = attn @ ow + ob + prior   (in-place into sP)
    gemm64<64, 64>(sQ, sW, [&](int tt, int to, float4 (&a4)[8]) {
        float4 bo = *reinterpret_cast<const float4*>(&ob[to]);
        #pragma unroll
        for (int i = 0; i < 8; i++) {
            float4 p = *reinterpret_cast<const float4*>(&sP[(tt + i) * 68 + to]);
            float4 r;
            r.x = a4[i].x + bo.x + p.x;
            r.y = a4[i].y + bo.y + p.y;
            r.z = a4[i].z + bo.z + p.z;
            r.w = a4[i].w + bo.w + p.w;
            *reinterpret_cast<float4*>(&sP[(tt + i) * 68 + to]) = r;
        }
    });
    __syncthreads();

    // ---- LN2 stats on h
    if (tid < 128) {
        float sum = 0.f, sq = 0.f;
        const float* rowp = sP + tid * 68;
        #pragma unroll
        for (int c = 0; c < 64; c += 4) {
            float4 v = *reinterpret_cast<const float4*>(rowp + c);
            sum += v.x + v.y + v.z + v.w;
            sq += v.x * v.x + v.y * v.y + v.z * v.z + v.w * v.w;
        }
        float mu = sum * (1.f / 64.f);
        float var = fmaxf(sq * (1.f / 64.f) - mu * mu, 0.f);
        sMu[tid] = mu;
        sRs[tid] = rsqrtf(var + 1e-5f);
    }
    __syncthreads();
    // hn -> sA (stride 64); ffn accumulator init with fc2 bias -> sV
    for (int i = tid; i < 2048; i += 256) {
        int t = i >> 4, c4 = (i & 15) * 4;
        float4 p = *reinterpret_cast<const float4*>(&sP[t * 68 + c4]);
        float4 w2 = *reinterpret_cast<const float4*>(&ln2w[c4]);
        float4 b2 = *reinterpret_cast<const float4*>(&ln2b[c4]);
        float4 fb = *reinterpret_cast<const float4*>(&fc2b[c4]);
        float mu = sMu[t], rs = sRs[t];
        float4 o;
        o.x = (p.x - mu) * rs * w2.x + b2.x;
        o.y = (p.y - mu) * rs * w2.y + b2.y;
        o.z = (p.z - mu) * rs * w2.z + b2.z;
        o.w = (p.w - mu) * rs * w2.w + b2.w;
        *reinterpret_cast<float4*>(&sA[t * 64 + c4]) = o;
        *reinterpret_cast<float4*>(&sV[t * 64 + c4]) = fb;
    }
    __syncthreads();

    // ---- FFN in 4 j-blocks of 64: t1 = gelu(hn@fc1_blk+b); acc += t1@fc2_blk
    for (int jb = 0; jb < 4; jb++) {
        for (int i = tid; i < 1024; i += 256) {
            int c = i >> 4, j4 = (i & 15) * 4;
            *reinterpret_cast<float4*>(&sW[c * 64 + j4]) =
                *reinterpret_cast<const float4*>(&fc1w[c * 256 + jb * 64 + j4]);
            reinterpret_cast<float4*>(sW + 4096)[i] =
                reinterpret_cast<const float4*>(fc2w + jb * 4096)[i];
        }
        __syncthreads();
        const float* f1b = fc1b + jb * 64;
        gemm64<64, 64>(sA, sW, [&](int tt, int to, float4 (&a4)[8]) {
            float4 b1 = *reinterpret_cast<const float4*>(&f1b[to]);
            #pragma unroll
            for (int i = 0; i < 8; i++) {
                float vx = a4[i].x + b1.x, vy = a4[i].y + b1.y;
                float vz = a4[i].z + b1.z, vw = a4[i].w + b1.w;
                float4 r;
                r.x = 0.5f * vx * (1.f + erff(vx * 0.70710678118654752f));
                r.y = 0.5f * vy * (1.f + erff(vy * 0.70710678118654752f));
                r.z = 0.5f * vz * (1.f + erff(vz * 0.70710678118654752f));
                r.w = 0.5f * vw * (1.f + erff(vw * 0.70710678118654752f));
                *reinterpret_cast<float4*>(&sQ[(tt + i) * 64 + to]) = r;
            }
        });
        __syncthreads();
        gemm64<64, 64>(sQ, sW + 4096, [&](int tt, int to, float4 (&a4)[8]) {
            #pragma unroll
            for (int i = 0; i < 8; i++) {
                float4 v = *reinterpret_cast<const float4*>(&sV[(tt + i) * 64 + to]);
                v.x += a4[i].x; v.y += a4[i].y; v.z += a4[i].z; v.w += a4[i].w;
                *reinterpret_cast<float4*>(&sV[(tt + i) * 64 + to]) = v;
            }
        });
        __syncthreads();
    }

    // ---- h += ffn; stage conv_w transposed (stride 68); load gamma/beta
    for (int i = tid; i < 2048; i += 256) {
        int t = i >> 4, c4 = (i & 15) * 4;
        float4 h = *reinterpret_cast<const float4*>(&sP[t * 68 + c4]);
        float4 f = *reinterpret_cast<const float4*>(&sV[t * 64 + c4]);
        h.x += f.x; h.y += f.y; h.z += f.z; h.w += f.w;
        *reinterpret_cast<float4*>(&sP[t * 68 + c4]) = h;
    }
    for (int i = tid; i < 1024; i += 256) {
        int o = i >> 4, i4 = (i & 15) * 4;
        float4 v = *reinterpret_cast<const float4*>(&cw[o * 64 + i4]);
        sW[(i4 + 0) * 68 + o] = v.x;   // conv_w is [out,in] -> [in][out]
        sW[(i4 + 1) * 68 + o] = v.y;
        sW[(i4 + 2) * 68 + o] = v.z;
        sW[(i4 + 3) * 68 + o] = v.w;
    }
    if (tid < 64) {
        sGm[tid] = g_film[b * 128 + tid];
        sBt[tid] = g_film[b * 128 + 64 + tid];
    }
    __syncthreads();

    // ---- conv(1x1) + conv_b + x, then FiLM: (1+g)*v + beta  -> sA (stride 68)
    gemm64<68, 68>(sP, sW, [&](int tt, int to, float4 (&a4)[8]) {
        float4 bc = *reinterpret_cast<const float4*>(&cb[to]);
        float4 g = *reinterpret_cast<const float4*>(&sGm[to]);
        float4 bt = *reinterpret_cast<const float4*>(&sBt[to]);
        #pragma unroll
        for (int i = 0; i < 8; i++) {
            float4 xr = *reinterpret_cast<const float4*>(&sX[(tt + i) * 68 + to]);
            float vx = a4[i].x + bc.x + xr.x;
            float vy = a4[i].y + bc.y + xr.y;
            float vz = a4[i].z + bc.z + xr.z;
            float vw = a4[i].w + bc.w + xr.w;
            float4 r;
            r.x = vx + g.x * vx + bt.x;
            r.y = vy + g.y * vy + bt.y;
            r.z = vz + g.z * vz + bt.z;
            r.w = vw + g.w * vw + bt.w;
            *reinterpret_cast<float4*>(&sA[(tt + i) * 68 + to]) = r;
        }
    });
    __syncthreads();

    // ---- write out coalesced channel-major
    for (int i = tid; i < 8192; i += 256) {
        int c = i >> 7, w_ = i & 127;
        out[base + (size_t)c * NPIX + w_] = sA[w_ * 68 + c];
    }
}

// ---------------------------------------------------------------------------
extern "C" void kernel_launch(void* const* d_in, const int* in_sizes, int n_in,
                              void* d_out, int out_size) {
    const float* x    = (const float*)d_in[0];
    const float* te   = (const float*)d_in[1];
    const float* qw   = (const float*)d_in[2];
    const float* qb   = (const float*)d_in[3];
    const float* kw   = (const float*)d_in[4];
    const float* kb   = (const float*)d_in[5];
    const float* vw   = (const float*)d_in[6];
    const float* vb   = (const float*)d_in[7];
    const float* ow   = (const float*)d_in[8];
    const float* ob   = (const float*)d_in[9];
    const float* ln1w = (const float*)d_in[10];
    const float* ln1b = (const float*)d_in[11];
    const float* ln2w = (const float*)d_in[12];
    const float* ln2b = (const float*)d_in[13];
    const float* fc1w = (const float*)d_in[14];
    const float* fc1b = (const float*)d_in[15];
    const float* fc2w = (const float*)d_in[16];
    const float* fc2b = (const float*)d_in[17];
    const float* cw   = (const float*)d_in[18];
    const float* cb   = (const float*)d_in[19];
    const float* m1w  = (const float*)d_in[20];
    const float* m1b  = (const float*)d_in[21];
    const float* m2w  = (const float*)d_in[22];
    const float* m2b  = (const float*)d_in[23];
    float* out = (float*)d_out;

    cudaFuncSetAttribute(fused_kernel, cudaFuncAttributeMaxDynamicSharedMemorySize,
                         SMEM_BYTES);

    pool_kernel<<<2048, 128>>>(te);
    film_kernel<<<8, 128>>>(m1w, m1b, m2w, m2b);
    fused_kernel<<<1024, 256, SMEM_BYTES>>>(x, te, qw, qb, kw, kb, vw, vb, ow, ob,
                                            ln1w, ln1b, ln2w, ln2b, fc1w, fc1b,
                                            fc2w, fc2b, cw, cb, out);
}